// round 15
// baseline (speedup 1.0000x reference)
#include <cuda_runtime.h>
#include <cuda_fp16.h>
#include <cstdint>

// ---------------------------------------------------------------------------
// LIF layer: Wx = x @ W^T via legacy mma.sync fp16x2-split (3-term) GEMM,
// fp32-equivalent accuracy. W pre-scaled by 2^10 (exact); 2^-10 folded into
// (1-alpha) in the scan (exact).
// R15: 2-way split DAG — G1(rows 0..31999) -> {S1(b 0..31) || G2(rows
// 32000..63999)} -> S2(b 32..63). S1 hides under G2; wave count unchanged
// (7+7 = 14 = unsplit makespan). Kernel interiors identical to R12.
// ---------------------------------------------------------------------------

static constexpr int Bb = 64;
static constexpr int Tt = 1000;
static constexpr int Ii = 1024;    // K
static constexpr int Hh = 1024;    // N
static constexpr int Mm = Bb * Tt; // 64000

__device__ float g_Wx[(size_t)Mm * Hh];   // 262 MB scratch (holds 2^10 * Wx)

// ----------------------------- GEMM config ---------------------------------
static constexpr int BM = 128;
static constexpr int BN = 128;
static constexpr int BK = 16;                  // one k16 step per chunk
static constexpr int NCHUNK = Ii / BK;         // 64

static constexpr int ROW_BYTES = 5 * 8;                 // 40
static constexpr int VAR_BYTES = 128 * ROW_BYTES;       // 5120
static constexpr int V_AHI = 0;
static constexpr int V_ALO = 1 * VAR_BYTES;
static constexpr int V_BHI = 2 * VAR_BYTES;
static constexpr int V_BLO = 3 * VAR_BYTES;
static constexpr int BUFSZ = 4 * VAR_BYTES;             // 20480
static constexpr int SMEM_TOTAL = 2 * BUFSZ;            // 40960 per CTA -> 2 CTAs/SM

__device__ __forceinline__ void mma_f16(float* d, const uint32_t* a, const uint32_t* b) {
    asm volatile(
        "mma.sync.aligned.m16n8k16.row.col.f32.f16.f16.f32 "
        "{%0,%1,%2,%3}, {%4,%5,%6,%7}, {%8,%9}, {%0,%1,%2,%3};"
        : "+f"(d[0]), "+f"(d[1]), "+f"(d[2]), "+f"(d[3])
        : "r"(a[0]), "r"(a[1]), "r"(a[2]), "r"(a[3]), "r"(b[0]), "r"(b[1]));
}

__device__ __forceinline__ uint32_t pack_h2(__half a, __half b) {
    return (uint32_t)__half_as_ushort(a) | ((uint32_t)__half_as_ushort(b) << 16);
}

__device__ __forceinline__ void split_f16(float v, __half& hi, __half& lo) {
    hi = __float2half_rn(v);
    lo = __float2half_rn(v - __half2float(hi));
}

__global__ __launch_bounds__(256, 2) void gemm_f16x2_mma(
    const float* __restrict__ A, const float* __restrict__ Bw, int m_base)
{
    extern __shared__ char smem[];
    const int tid  = threadIdx.x;
    const int wid  = tid >> 5;
    const int lane = tid & 31;
    const int grp  = lane >> 2;     // 0..7
    const int tig  = lane & 3;      // 0..3
    const int warp_m = wid & 1;     // 2 warps in M
    const int warp_n = wid >> 1;    // 4 warps in N
    const int m0w = warp_m * 64;
    const int n0w = warp_n * 32;
    const int bm = m_base + blockIdx.y * BM;
    const int bn = blockIdx.x * BN;

    float acc[4][4][4];
#pragma unroll
    for (int i = 0; i < 4; i++)
#pragma unroll
        for (int j = 0; j < 4; j++)
#pragma unroll
            for (int k = 0; k < 4; k++) acc[i][j][k] = 0.0f;

    int fm[2], fkq[2];
#pragma unroll
    for (int i = 0; i < 2; i++) {
        int f = i * 256 + tid;          // 0..511
        fm[i]  = f >> 2;                // 0..127
        fkq[i] = (f & 3) * 4;           // 0,4,8,12
    }

    float4 va[2], vb[2];

    auto ldg_chunk = [&](int k0) {
#pragma unroll
        for (int i = 0; i < 2; i++) {
            va[i] = *(const float4*)(A  + (size_t)(bm + fm[i]) * Ii + k0 + fkq[i]);
            vb[i] = *(const float4*)(Bw + (size_t)(bn + fm[i]) * Ii + k0 + fkq[i]);
        }
    };

    auto sts_chunk = [&](int buf) {
        char* base = smem + buf * BUFSZ;
#pragma unroll
        for (int i = 0; i < 2; i++) {
            const int word  = (fkq[i] >= 8) ? 4 : 0;
            const int cell0 = (fkq[i] & 7) >> 1;
            const uint32_t off = (uint32_t)(fm[i] * ROW_BYTES + cell0 * 8 + word);
            {
                __half h0, l0, h1, l1, h2, l2, h3, l3;
                split_f16(va[i].x, h0, l0); split_f16(va[i].y, h1, l1);
                split_f16(va[i].z, h2, l2); split_f16(va[i].w, h3, l3);
                *(uint32_t*)(base + V_AHI + off)     = pack_h2(h0, h1);
                *(uint32_t*)(base + V_AHI + off + 8) = pack_h2(h2, h3);
                *(uint32_t*)(base + V_ALO + off)     = pack_h2(l0, l1);
                *(uint32_t*)(base + V_ALO + off + 8) = pack_h2(l2, l3);
            }
            {   // B scaled by 2^10 so lo stays in fp16 normal range
                __half h0, l0, h1, l1, h2, l2, h3, l3;
                split_f16(vb[i].x * 1024.0f, h0, l0); split_f16(vb[i].y * 1024.0f, h1, l1);
                split_f16(vb[i].z * 1024.0f, h2, l2); split_f16(vb[i].w * 1024.0f, h3, l3);
                *(uint32_t*)(base + V_BHI + off)     = pack_h2(h0, h1);
                *(uint32_t*)(base + V_BHI + off + 8) = pack_h2(h2, h3);
                *(uint32_t*)(base + V_BLO + off)     = pack_h2(l0, l1);
                *(uint32_t*)(base + V_BLO + off + 8) = pack_h2(l2, l3);
            }
        }
    };

    ldg_chunk(0);
    sts_chunk(0);
    __syncthreads();

    for (int c = 0; c < NCHUNK; c++) {
        const int cur = c & 1;
        const char* p = smem + cur * BUFSZ;

        if (c + 1 < NCHUNK) ldg_chunk((c + 1) * BK);   // prefetch overlaps MMA

        uint32_t bh[4][2], bl[4][2];
#pragma unroll
        for (int nt = 0; nt < 4; nt++) {
            const int n = n0w + nt * 8 + grp;
            uint2 h = *(const uint2*)(p + V_BHI + n * ROW_BYTES + tig * 8);
            uint2 l = *(const uint2*)(p + V_BLO + n * ROW_BYTES + tig * 8);
            bh[nt][0] = h.x; bh[nt][1] = h.y;
            bl[nt][0] = l.x; bl[nt][1] = l.y;
        }

#pragma unroll
        for (int mp = 0; mp < 2; mp++) {
            uint32_t ah[2][4], al[2][4];
#pragma unroll
            for (int q = 0; q < 2; q++) {
                const int m = m0w + (mp * 2 + q) * 16 + grp;
                uint2 h0 = *(const uint2*)(p + V_AHI + m * ROW_BYTES + tig * 8);
                uint2 h1 = *(const uint2*)(p + V_AHI + (m + 8) * ROW_BYTES + tig * 8);
                uint2 l0 = *(const uint2*)(p + V_ALO + m * ROW_BYTES + tig * 8);
                uint2 l1 = *(const uint2*)(p + V_ALO + (m + 8) * ROW_BYTES + tig * 8);
                ah[q][0] = h0.x; ah[q][1] = h1.x; ah[q][2] = h0.y; ah[q][3] = h1.y;
                al[q][0] = l0.x; al[q][1] = l1.x; al[q][2] = l0.y; al[q][3] = l1.y;
            }
#pragma unroll
            for (int q = 0; q < 2; q++)
#pragma unroll
                for (int nt = 0; nt < 4; nt++)
                    mma_f16(acc[mp * 2 + q][nt], ah[q], bh[nt]);   // hi*hi
#pragma unroll
            for (int q = 0; q < 2; q++)
#pragma unroll
                for (int nt = 0; nt < 4; nt++)
                    mma_f16(acc[mp * 2 + q][nt], ah[q], bl[nt]);   // hi*lo
#pragma unroll
            for (int q = 0; q < 2; q++)
#pragma unroll
                for (int nt = 0; nt < 4; nt++)
                    mma_f16(acc[mp * 2 + q][nt], al[q], bh[nt]);   // lo*hi
        }

        if (c + 1 < NCHUNK) sts_chunk(cur ^ 1);
        __syncthreads();
    }

#pragma unroll
    for (int mt = 0; mt < 4; mt++) {
#pragma unroll
        for (int nt = 0; nt < 4; nt++) {
            const int row = bm + m0w + mt * 16 + grp;
            const int col = bn + n0w + nt * 8 + tig * 2;
            *(float2*)&g_Wx[(size_t)row * Hh + col] =
                make_float2(acc[mt][nt][0], acc[mt][nt][1]);
            *(float2*)&g_Wx[(size_t)(row + 8) * Hh + col] =
                make_float2(acc[mt][nt][2], acc[mt][nt][3]);
        }
    }
}

// ------------------------------- LIF scan ------------------------------------
static constexpr int UNR = 20;   // 1000 = 50 * 20

__global__ __launch_bounds__(128) void lif_scan_kernel(
    const float* __restrict__ alpha,
    const float* __restrict__ u0,
    const float* __restrict__ s0,
    float* __restrict__ out, int b_base)
{
    const int g = blockIdx.x * blockDim.x + threadIdx.x;   // 0 .. 32767
    const int h = g & (Hh - 1);
    const int b = b_base + (g >> 10);

    const float AMIN = 0.81873075307798185867f;  // exp(-1/5)
    const float AMAX = 0.96078943915232320938f;  // exp(-1/25)

    float a = alpha[h];
    a = fminf(fmaxf(a, AMIN), AMAX);
    // g_Wx holds 2^10 * Wx; fold 2^-10 (exact) into (1 - a)
    const float omas = (1.0f - a) * 0.0009765625f;

    float u = u0[b * Hh + h];
    float s = s0[b * Hh + h];

    const float* wxp = g_Wx + (size_t)b * Tt * Hh + h;
    float* op = out + (size_t)b * Tt * Hh + h;

    for (int t0 = 0; t0 < Tt; t0 += UNR) {
        float wx[UNR];
#pragma unroll
        for (int i = 0; i < UNR; i++)
            wx[i] = __ldcs(wxp + (size_t)(t0 + i) * Hh);
#pragma unroll
        for (int i = 0; i < UNR; i++) {
            u = a * (u - s) + omas * wx[i];
            s = (u > 1.0f) ? 1.0f : 0.0f;
            __stcs(op + (size_t)(t0 + i) * Hh, s);
        }
    }
}

// ------------------------------- launch --------------------------------------
extern "C" void kernel_launch(void* const* d_in, const int* in_sizes, int n_in,
                              void* d_out, int out_size)
{
    const float* x     = (const float*)d_in[0];  // [B, T, I]
    const float* W     = (const float*)d_in[1];  // [H, I]
    const float* alpha = (const float*)d_in[2];  // [H]
    const float* u0    = (const float*)d_in[3];  // [B, H]
    const float* s0    = (const float*)d_in[4];  // [B, H]
    float* out = (float*)d_out;

    (void)in_sizes; (void)n_in; (void)out_size;

    static bool init = false;
    static cudaStream_t s2;
    static cudaEvent_t e1, e2;
    if (!init) {
        cudaStreamCreateWithFlags(&s2, cudaStreamNonBlocking);
        cudaEventCreateWithFlags(&e1, cudaEventDisableTiming);
        cudaEventCreateWithFlags(&e2, cudaEventDisableTiming);
        cudaFuncSetAttribute(gemm_f16x2_mma,
                             cudaFuncAttributeMaxDynamicSharedMemorySize, SMEM_TOTAL);
        init = true;
    }

    const dim3 ggrid(Hh / BN, (Mm / 2) / BM);   // (8, 250) per half
    const int  sgrid = (Bb / 2) * Hh / 128;     // 256 blocks per half

    // G1: rows [0, 32000)
    gemm_f16x2_mma<<<ggrid, 256, SMEM_TOTAL>>>(x, W, 0);
    cudaEventRecord(e1, 0);

    // S1 (b 0..31) on side stream, after G1; overlaps G2
    cudaStreamWaitEvent(s2, e1, 0);
    lif_scan_kernel<<<sgrid, 128, 0, s2>>>(alpha, u0, s0, out, 0);
    cudaEventRecord(e2, s2);

    // G2: rows [32000, 64000), then S2 (b 32..63) on main stream
    gemm_f16x2_mma<<<ggrid, 256, SMEM_TOTAL>>>(x, W, Mm / 2);
    lif_scan_kernel<<<sgrid, 128>>>(alpha, u0, s0, out, Bb / 2);

    // rejoin: graph end waits for S1
    cudaStreamWaitEvent(0, e2, 0);
}

// round 17
// speedup vs baseline: 1.1181x; 1.1181x over previous
#include <cuda_runtime.h>
#include <cuda_fp16.h>
#include <cstdint>

// ---------------------------------------------------------------------------
// LIF layer: Wx = x @ W^T via legacy mma.sync fp16x2-split (3-term) GEMM,
// fp32-equivalent accuracy. W pre-scaled by 2^10 (exact); 2^-10 folded into
// (1-alpha) in the scan (exact).
// FINAL = R12/R9 verbatim — best measured configuration (1435.5 us,
// rel_err 0.0, reproduced three times). GEMM at 99% of the legacy fp16 HMMA
// pipe floor (~512 MAC/cyc/SM); scan at its occupancy-limited HBM wall.
// Rejected with measurements: tcgen05 (compute_103 virtual arch blocks it),
// tf32x3 (256 MAC/cyc/SM — 2x slower), persistence (x2 regressions),
// split-DAG overlap (double tail + interference), scan pipelining (neutral),
// float2 scan (occupancy loss), fewer split terms (spike-flip error budget).
// ---------------------------------------------------------------------------

static constexpr int Bb = 64;
static constexpr int Tt = 1000;
static constexpr int Ii = 1024;    // K
static constexpr int Hh = 1024;    // N
static constexpr int Mm = Bb * Tt; // 64000

__device__ float g_Wx[(size_t)Mm * Hh];   // 262 MB scratch (holds 2^10 * Wx)

// ----------------------------- GEMM config ---------------------------------
static constexpr int BM = 128;
static constexpr int BN = 128;
static constexpr int BK = 16;                  // one k16 step per chunk
static constexpr int NCHUNK = Ii / BK;         // 64

// smem per variant: cell[row][tig] = uint2{ pack(k=2t,2t+1), pack(k=2t+8,2t+9) }
// row stride 5 uint2 (40B) to break bank conflicts.
static constexpr int ROW_BYTES = 5 * 8;                 // 40
static constexpr int VAR_BYTES = 128 * ROW_BYTES;       // 5120
static constexpr int V_AHI = 0;
static constexpr int V_ALO = 1 * VAR_BYTES;
static constexpr int V_BHI = 2 * VAR_BYTES;
static constexpr int V_BLO = 3 * VAR_BYTES;
static constexpr int BUFSZ = 4 * VAR_BYTES;             // 20480
static constexpr int SMEM_TOTAL = 2 * BUFSZ;            // 40960 per CTA -> 2 CTAs/SM

__device__ __forceinline__ void mma_f16(float* d, const uint32_t* a, const uint32_t* b) {
    asm volatile(
        "mma.sync.aligned.m16n8k16.row.col.f32.f16.f16.f32 "
        "{%0,%1,%2,%3}, {%4,%5,%6,%7}, {%8,%9}, {%0,%1,%2,%3};"
        : "+f"(d[0]), "+f"(d[1]), "+f"(d[2]), "+f"(d[3])
        : "r"(a[0]), "r"(a[1]), "r"(a[2]), "r"(a[3]), "r"(b[0]), "r"(b[1]));
}

__device__ __forceinline__ uint32_t pack_h2(__half a, __half b) {
    return (uint32_t)__half_as_ushort(a) | ((uint32_t)__half_as_ushort(b) << 16);
}

// split float into (hi, lo) fp16 halves
__device__ __forceinline__ void split_f16(float v, __half& hi, __half& lo) {
    hi = __float2half_rn(v);
    lo = __float2half_rn(v - __half2float(hi));
}

__global__ __launch_bounds__(256, 2) void gemm_f16x2_mma(
    const float* __restrict__ A, const float* __restrict__ Bw)
{
    extern __shared__ char smem[];
    const int tid  = threadIdx.x;
    const int wid  = tid >> 5;
    const int lane = tid & 31;
    const int grp  = lane >> 2;     // 0..7
    const int tig  = lane & 3;      // 0..3
    const int warp_m = wid & 1;     // 2 warps in M
    const int warp_n = wid >> 1;    // 4 warps in N
    const int m0w = warp_m * 64;
    const int n0w = warp_n * 32;
    const int bm = blockIdx.y * BM;
    const int bn = blockIdx.x * BN;

    float acc[4][4][4];
#pragma unroll
    for (int i = 0; i < 4; i++)
#pragma unroll
        for (int j = 0; j < 4; j++)
#pragma unroll
            for (int k = 0; k < 4; k++) acc[i][j][k] = 0.0f;

    // fill coordinates: 2 float4 of A and 2 of B per chunk per thread
    int fm[2], fkq[2];
#pragma unroll
    for (int i = 0; i < 2; i++) {
        int f = i * 256 + tid;          // 0..511
        fm[i]  = f >> 2;                // 0..127
        fkq[i] = (f & 3) * 4;           // 0,4,8,12
    }

    float4 va[2], vb[2];

    auto ldg_chunk = [&](int k0) {
#pragma unroll
        for (int i = 0; i < 2; i++) {
            va[i] = *(const float4*)(A  + (size_t)(bm + fm[i]) * Ii + k0 + fkq[i]);
            vb[i] = *(const float4*)(Bw + (size_t)(bn + fm[i]) * Ii + k0 + fkq[i]);
        }
    };

    // float4 at k-quad kq covers half-pairs (kq,kq+1),(kq+2,kq+3):
    // pair (k,k+1), k even: k<8 -> cell[k/2] word0 ; k>=8 -> cell[(k-8)/2] word1
    auto sts_chunk = [&](int buf) {
        char* base = smem + buf * BUFSZ;
#pragma unroll
        for (int i = 0; i < 2; i++) {
            const int word  = (fkq[i] >= 8) ? 4 : 0;           // byte offset of word
            const int cell0 = (fkq[i] & 7) >> 1;               // first cell index
            const uint32_t off = (uint32_t)(fm[i] * ROW_BYTES + cell0 * 8 + word);

            // A: unscaled
            {
                __half h0, l0, h1, l1, h2, l2, h3, l3;
                split_f16(va[i].x, h0, l0); split_f16(va[i].y, h1, l1);
                split_f16(va[i].z, h2, l2); split_f16(va[i].w, h3, l3);
                *(uint32_t*)(base + V_AHI + off)     = pack_h2(h0, h1);
                *(uint32_t*)(base + V_AHI + off + 8) = pack_h2(h2, h3);
                *(uint32_t*)(base + V_ALO + off)     = pack_h2(l0, l1);
                *(uint32_t*)(base + V_ALO + off + 8) = pack_h2(l2, l3);
            }
            // B: scaled by 2^10 so lo stays in fp16 normal range
            {
                __half h0, l0, h1, l1, h2, l2, h3, l3;
                split_f16(vb[i].x * 1024.0f, h0, l0); split_f16(vb[i].y * 1024.0f, h1, l1);
                split_f16(vb[i].z * 1024.0f, h2, l2); split_f16(vb[i].w * 1024.0f, h3, l3);
                *(uint32_t*)(base + V_BHI + off)     = pack_h2(h0, h1);
                *(uint32_t*)(base + V_BHI + off + 8) = pack_h2(h2, h3);
                *(uint32_t*)(base + V_BLO + off)     = pack_h2(l0, l1);
                *(uint32_t*)(base + V_BLO + off + 8) = pack_h2(l2, l3);
            }
        }
    };

    ldg_chunk(0);
    sts_chunk(0);
    __syncthreads();

    for (int c = 0; c < NCHUNK; c++) {
        const int cur = c & 1;
        const char* p = smem + cur * BUFSZ;

        if (c + 1 < NCHUNK) ldg_chunk((c + 1) * BK);   // prefetch overlaps MMA

        // B fragments: 4 n-tiles x {hi,lo}, 1 LDS.64 each (b0=word0, b1=word1)
        uint32_t bh[4][2], bl[4][2];
#pragma unroll
        for (int nt = 0; nt < 4; nt++) {
            const int n = n0w + nt * 8 + grp;
            uint2 h = *(const uint2*)(p + V_BHI + n * ROW_BYTES + tig * 8);
            uint2 l = *(const uint2*)(p + V_BLO + n * ROW_BYTES + tig * 8);
            bh[nt][0] = h.x; bh[nt][1] = h.y;
            bl[nt][0] = l.x; bl[nt][1] = l.y;
        }

        // mt pairs, variant-major: same-acc reuse distance = 8 HMMAs
#pragma unroll
        for (int mp = 0; mp < 2; mp++) {
            uint32_t ah[2][4], al[2][4];
#pragma unroll
            for (int q = 0; q < 2; q++) {
                const int m = m0w + (mp * 2 + q) * 16 + grp;
                uint2 h0 = *(const uint2*)(p + V_AHI + m * ROW_BYTES + tig * 8);
                uint2 h1 = *(const uint2*)(p + V_AHI + (m + 8) * ROW_BYTES + tig * 8);
                uint2 l0 = *(const uint2*)(p + V_ALO + m * ROW_BYTES + tig * 8);
                uint2 l1 = *(const uint2*)(p + V_ALO + (m + 8) * ROW_BYTES + tig * 8);
                ah[q][0] = h0.x; ah[q][1] = h1.x; ah[q][2] = h0.y; ah[q][3] = h1.y;
                al[q][0] = l0.x; al[q][1] = l1.x; al[q][2] = l0.y; al[q][3] = l1.y;
            }
#pragma unroll
            for (int q = 0; q < 2; q++)
#pragma unroll
                for (int nt = 0; nt < 4; nt++)
                    mma_f16(acc[mp * 2 + q][nt], ah[q], bh[nt]);   // hi*hi
#pragma unroll
            for (int q = 0; q < 2; q++)
#pragma unroll
                for (int nt = 0; nt < 4; nt++)
                    mma_f16(acc[mp * 2 + q][nt], ah[q], bl[nt]);   // hi*lo
#pragma unroll
            for (int q = 0; q < 2; q++)
#pragma unroll
                for (int nt = 0; nt < 4; nt++)
                    mma_f16(acc[mp * 2 + q][nt], al[q], bh[nt]);   // lo*hi
        }

        if (c + 1 < NCHUNK) sts_chunk(cur ^ 1);
        __syncthreads();
    }

    // epilogue: registers -> g_Wx (float2 stores)
#pragma unroll
    for (int mt = 0; mt < 4; mt++) {
#pragma unroll
        for (int nt = 0; nt < 4; nt++) {
            const int row = bm + m0w + mt * 16 + grp;
            const int col = bn + n0w + nt * 8 + tig * 2;
            *(float2*)&g_Wx[(size_t)row * Hh + col] =
                make_float2(acc[mt][nt][0], acc[mt][nt][1]);
            *(float2*)&g_Wx[(size_t)(row + 8) * Hh + col] =
                make_float2(acc[mt][nt][2], acc[mt][nt][3]);
        }
    }
}

// ------------------------------- LIF scan ------------------------------------
static constexpr int UNR = 20;   // 1000 = 50 * 20

__global__ __launch_bounds__(128) void lif_scan_kernel(
    const float* __restrict__ alpha,
    const float* __restrict__ u0,
    const float* __restrict__ s0,
    float* __restrict__ out)
{
    const int g = blockIdx.x * blockDim.x + threadIdx.x;
    if (g >= Bb * Hh) return;
    const int h = g & (Hh - 1);
    const int b = g >> 10;

    const float AMIN = 0.81873075307798185867f;  // exp(-1/5)
    const float AMAX = 0.96078943915232320938f;  // exp(-1/25)

    float a = alpha[h];
    a = fminf(fmaxf(a, AMIN), AMAX);
    // g_Wx holds 2^10 * Wx; fold 2^-10 (exact) into (1 - a)
    const float omas = (1.0f - a) * 0.0009765625f;

    float u = u0[g];
    float s = s0[g];

    const float* wxp = g_Wx + (size_t)b * Tt * Hh + h;
    float* op = out + (size_t)b * Tt * Hh + h;

    for (int t0 = 0; t0 < Tt; t0 += UNR) {
        float wx[UNR];
#pragma unroll
        for (int i = 0; i < UNR; i++)
            wx[i] = __ldcs(wxp + (size_t)(t0 + i) * Hh);
#pragma unroll
        for (int i = 0; i < UNR; i++) {
            u = a * (u - s) + omas * wx[i];
            s = (u > 1.0f) ? 1.0f : 0.0f;
            __stcs(op + (size_t)(t0 + i) * Hh, s);
        }
    }
}

// ------------------------------- launch --------------------------------------
extern "C" void kernel_launch(void* const* d_in, const int* in_sizes, int n_in,
                              void* d_out, int out_size)
{
    const float* x     = (const float*)d_in[0];  // [B, T, I]
    const float* W     = (const float*)d_in[1];  // [H, I]
    const float* alpha = (const float*)d_in[2];  // [H]
    const float* u0    = (const float*)d_in[3];  // [B, H]
    const float* s0    = (const float*)d_in[4];  // [B, H]
    float* out = (float*)d_out;

    (void)in_sizes; (void)n_in; (void)out_size;

    cudaFuncSetAttribute(gemm_f16x2_mma,
                         cudaFuncAttributeMaxDynamicSharedMemorySize, SMEM_TOTAL);

    dim3 grid(Hh / BN, Mm / BM);   // (8, 500)
    gemm_f16x2_mma<<<grid, 256, SMEM_TOTAL>>>(x, W);

    lif_scan_kernel<<<(Bb * Hh) / 128, 128>>>(alpha, u0, s0, out);
}